// round 1
// baseline (speedup 1.0000x reference)
#include <cuda_runtime.h>
#include <math.h>

#define NB   16
#define C0   128
#define H8   44
#define W8   144
#define HWLO (H8 * W8)          // 6336
#define NPIX (NB * HWLO)        // 101376 = 396 * 256
#define HOUT (H8 * 8)           // 352
#define WOUT (W8 * 8)           // 1152
#define PI_F 3.1415926535f
#define MAX_DEPTH 81.0f

// ---------------- shared-weight loaders (transpose [O,C] -> [C,O]) -------------
template<int CIN, int COUT>
__device__ __forceinline__ void load_wT(const float* __restrict__ g, float* s, int t, int nt) {
    for (int i = t; i < CIN * COUT; i += nt) {
        int c = i / COUT, o = i % COUT;
        s[i] = g[o * CIN + c];
    }
}

__device__ __forceinline__ void load_vec(const float* __restrict__ g, float* s, int n, int t, int nt) {
    for (int i = t; i < n; i += nt) s[i] = g[i];
}

// ---------------- dense layer: out[o] = b[o] + sum_c wT[c*COUT+o] * in[c] ------
template<int CIN, int COUT, bool DO_ELU>
__device__ __forceinline__ void dense(const float* __restrict__ sW,
                                      const float* __restrict__ sB,
                                      const float* __restrict__ in,
                                      float* __restrict__ outv) {
#pragma unroll
    for (int o = 0; o < COUT; o++) outv[o] = sB[o];
#pragma unroll 4
    for (int c = 0; c < CIN; c++) {
        float xc = in[c];
#pragma unroll
        for (int o = 0; o < COUT; o++) outv[o] += sW[c * COUT + o] * xc;
    }
    if (DO_ELU) {
#pragma unroll
        for (int o = 0; o < COUT; o++) {
            float v = outv[o];
            outv[o] = (v > 0.0f) ? v : (__expf(v) - 1.0f);
        }
    }
}

__device__ __forceinline__ float sigmoidf_fast(float v) {
    return __fdividef(1.0f, 1.0f + __expf(-v));
}

// ---------------------------------- kernel ------------------------------------
__global__ __launch_bounds__(256) void lpg_fused_kernel(
    const float* __restrict__ x,
    const float* __restrict__ w0, const float* __restrict__ b0,
    const float* __restrict__ w1, const float* __restrict__ b1,
    const float* __restrict__ w2, const float* __restrict__ b2,
    const float* __restrict__ w3, const float* __restrict__ b3,
    const float* __restrict__ w4, const float* __restrict__ b4,
    const float* __restrict__ wc, const float* __restrict__ bc,
    float* __restrict__ out)
{
    __shared__ __align__(16) float sW0[128 * 64];
    __shared__ __align__(16) float sW1[64 * 32];
    __shared__ __align__(16) float sW2[32 * 16];
    __shared__ __align__(16) float sW3[16 * 8];
    __shared__ __align__(16) float sW4[8 * 4];
    __shared__ __align__(16) float sWc[4 * 3];
    __shared__ float sB0[64], sB1[32], sB2[16], sB3[8], sB4[4], sBc[3];

    const int t = threadIdx.x;
    load_wT<128, 64>(w0, sW0, t, 256);
    load_wT<64, 32>(w1, sW1, t, 256);
    load_wT<32, 16>(w2, sW2, t, 256);
    load_wT<16, 8>(w3, sW3, t, 256);
    load_wT<8, 4>(w4, sW4, t, 256);
    load_wT<4, 3>(wc, sWc, t, 256);
    load_vec(b0, sB0, 64, t, 256);
    load_vec(b1, sB1, 32, t, 256);
    load_vec(b2, sB2, 16, t, 256);
    load_vec(b3, sB3, 8, t, 256);
    load_vec(b4, sB4, 4, t, 256);
    load_vec(bc, sBc, 3, t, 256);
    __syncthreads();

    const int p = blockIdx.x * 256 + t;
    if (p >= NPIX) return;
    const int b  = p / HWLO;
    const int hw = p - b * HWLO;

    // ---- layer 1: 128 -> 64, input streamed from global (coalesced across warp)
    const float* __restrict__ xp = x + (size_t)b * C0 * HWLO + hw;
    float a1[64];
#pragma unroll
    for (int o = 0; o < 64; o++) a1[o] = sB0[o];
#pragma unroll 4
    for (int c = 0; c < 128; c++) {
        float xc = __ldg(xp + (size_t)c * HWLO);
#pragma unroll
        for (int o = 0; o < 64; o++) a1[o] += sW0[c * 64 + o] * xc;
    }
#pragma unroll
    for (int o = 0; o < 64; o++) {
        float v = a1[o];
        a1[o] = (v > 0.0f) ? v : (__expf(v) - 1.0f);
    }

    float a2[32]; dense<64, 32, true >(sW1, sB1, a1, a2);
    float a3[16]; dense<32, 16, true >(sW2, sB2, a2, a3);
    float a4[8];  dense<16, 8,  true >(sW3, sB3, a3, a4);
    float a5[4];  dense<8,  4,  false>(sW4, sB4, a4, a5);   // no activation
    float y[3];   dense<4,  3,  false>(sWc, sBc, a5, y);

    // ---- plane parameters
    const float theta = sigmoidf_fast(y[0]) * (PI_F / 6.0f);
    const float phi   = sigmoidf_fast(y[1]) * (PI_F * 2.0f);
    const float dist  = sigmoidf_fast(y[2]) * MAX_DEPTH;

    const float st = __sinf(theta), ct = __cosf(theta);
    const float sp = __sinf(phi),   cp = __cosf(phi);
    float nx = st * cp, ny = st * sp, nz = ct;
    // F.normalize(p=2, dim=1, eps=1e-12): norm == 1 up to rounding, replicate anyway
    const float inv = rsqrtf(nx * nx + ny * ny + nz * nz);
    nx *= inv; ny *= inv; nz *= inv;

    // ---- 8x8 upsampled depth block
    const int h = hw / W8;
    const int w = hw - h * W8;
    float* __restrict__ op = out + ((size_t)b * HOUT + (size_t)h * 8) * WOUT + (size_t)w * 8;

#pragma unroll
    for (int i = 0; i < 8; i++) {
        const float vterm = ny * ((float)i - 3.5f) * 0.125f + nz;
        float row[8];
#pragma unroll
        for (int j = 0; j < 8; j++) {
            const float u = ((float)j - 3.5f) * 0.125f;
            row[j] = __fdividef(dist, nx * u + vterm);
        }
        float4* o4 = (float4*)(op + (size_t)i * WOUT);
        o4[0] = make_float4(row[0], row[1], row[2], row[3]);
        o4[1] = make_float4(row[4], row[5], row[6], row[7]);
    }
}

extern "C" void kernel_launch(void* const* d_in, const int* in_sizes, int n_in,
                              void* d_out, int out_size) {
    const float* x  = (const float*)d_in[0];
    const float* w0 = (const float*)d_in[1];
    const float* b0 = (const float*)d_in[2];
    const float* w1 = (const float*)d_in[3];
    const float* b1 = (const float*)d_in[4];
    const float* w2 = (const float*)d_in[5];
    const float* b2 = (const float*)d_in[6];
    const float* w3 = (const float*)d_in[7];
    const float* b3 = (const float*)d_in[8];
    const float* w4 = (const float*)d_in[9];
    const float* b4 = (const float*)d_in[10];
    const float* wc = (const float*)d_in[11];
    const float* bc = (const float*)d_in[12];
    float* out = (float*)d_out;

    lpg_fused_kernel<<<NPIX / 256, 256>>>(x, w0, b0, w1, b1, w2, b2, w3, b3,
                                          w4, b4, wc, bc, out);
}

// round 2
// speedup vs baseline: 1.6785x; 1.6785x over previous
#include <cuda_runtime.h>
#include <math.h>

#define NB   16
#define C0   128
#define H8   44
#define W8   144
#define HWLO (H8 * W8)          // 6336
#define NPIX (NB * HWLO)        // 101376 = 396 * 256
#define HOUT (H8 * 8)           // 352
#define WOUT (W8 * 8)           // 1152
#define PI_F 3.1415926535f
#define MAX_DEPTH 81.0f

typedef unsigned long long u64;

// ---------------- packed f32x2 helpers (sm_103a) -------------------------------
__device__ __forceinline__ u64 pack2(float lo, float hi) {
    u64 r; asm("mov.b64 %0, {%1, %2};" : "=l"(r) : "f"(lo), "f"(hi)); return r;
}
__device__ __forceinline__ void unpack2(u64 v, float& lo, float& hi) {
    asm("mov.b64 {%0, %1}, %2;" : "=f"(lo), "=f"(hi) : "l"(v));
}
__device__ __forceinline__ u64 fma2(u64 a, u64 b, u64 c) {
    u64 d; asm("fma.rn.f32x2 %0, %1, %2, %3;" : "=l"(d) : "l"(a), "l"(b), "l"(c));
    return d;
}

// ---------------- shared-weight loaders (transpose [O,C] -> [C,O]) -------------
template<int CIN, int COUT>
__device__ __forceinline__ void load_wT(const float* __restrict__ g, float* s, int t, int nt) {
    for (int i = t; i < CIN * COUT; i += nt) {
        int c = i / COUT, o = i % COUT;
        s[i] = g[o * CIN + c];
    }
}
__device__ __forceinline__ void load_vec(const float* __restrict__ g, float* s, int n, int t, int nt) {
    for (int i = t; i < n; i += nt) s[i] = g[i];
}

__device__ __forceinline__ float eluf(float v) {
    return (v > 0.0f) ? v : (__expf(v) - 1.0f);
}
__device__ __forceinline__ float sigmoidf_fast(float v) {
    return __fdividef(1.0f, 1.0f + __expf(-v));
}

// ---- packed dense layer: COUT even, accumulate pairs of output channels ------
template<int CIN, int COUTP, bool DO_ELU>
__device__ __forceinline__ void dense2(const float* __restrict__ sW,   // [CIN][2*COUTP]
                                       const float* __restrict__ sB,
                                       const float* __restrict__ in,
                                       float* __restrict__ outv) {
    const u64* __restrict__ w2 = (const u64*)sW;
    const u64* __restrict__ b2 = (const u64*)sB;
    u64 acc[COUTP];
#pragma unroll
    for (int j = 0; j < COUTP; j++) acc[j] = b2[j];
#pragma unroll 4
    for (int c = 0; c < CIN; c++) {
        const u64 xx = pack2(in[c], in[c]);
#pragma unroll
        for (int j = 0; j < COUTP; j++) acc[j] = fma2(w2[c * COUTP + j], xx, acc[j]);
    }
#pragma unroll
    for (int j = 0; j < COUTP; j++) {
        float lo, hi; unpack2(acc[j], lo, hi);
        if (DO_ELU) { lo = eluf(lo); hi = eluf(hi); }
        outv[2 * j] = lo; outv[2 * j + 1] = hi;
    }
}

// ---------------------------------- kernel ------------------------------------
__global__ __launch_bounds__(256, 2) void lpg_fused_kernel(
    const float* __restrict__ x,
    const float* __restrict__ w0, const float* __restrict__ b0,
    const float* __restrict__ w1, const float* __restrict__ b1,
    const float* __restrict__ w2, const float* __restrict__ b2,
    const float* __restrict__ w3, const float* __restrict__ b3,
    const float* __restrict__ w4, const float* __restrict__ b4,
    const float* __restrict__ wc, const float* __restrict__ bc,
    float* __restrict__ out)
{
    __shared__ __align__(16) float sW0[128 * 64];
    __shared__ __align__(16) float sW1[64 * 32];
    __shared__ __align__(16) float sW2[32 * 16];
    __shared__ __align__(16) float sW3[16 * 8];
    __shared__ __align__(16) float sW4[8 * 4];
    __shared__ __align__(16) float sWc[4 * 3];
    __shared__ __align__(16) float sB0[64];
    __shared__ __align__(16) float sB1[32];
    __shared__ __align__(16) float sB2[16];
    __shared__ __align__(16) float sB3[8];
    __shared__ __align__(16) float sB4[4];
    __shared__ float sBc[3];

    const int t = threadIdx.x;
    load_wT<128, 64>(w0, sW0, t, 256);
    load_wT<64, 32>(w1, sW1, t, 256);
    load_wT<32, 16>(w2, sW2, t, 256);
    load_wT<16, 8>(w3, sW3, t, 256);
    load_wT<8, 4>(w4, sW4, t, 256);
    load_wT<4, 3>(wc, sWc, t, 256);
    load_vec(b0, sB0, 64, t, 256);
    load_vec(b1, sB1, 32, t, 256);
    load_vec(b2, sB2, 16, t, 256);
    load_vec(b3, sB3, 8, t, 256);
    load_vec(b4, sB4, 4, t, 256);
    load_vec(bc, sBc, 3, t, 256);
    __syncthreads();

    const int p  = blockIdx.x * 256 + t;     // grid is exact: NPIX/256 blocks
    const int b  = p / HWLO;
    const int hw = p - b * HWLO;

    // ---- layer 1: 128 -> 64 in packed pairs, input streamed from global ------
    const float* __restrict__ xp = x + (size_t)b * C0 * HWLO + hw;
    const u64* __restrict__ sW0p = (const u64*)sW0;
    const u64* __restrict__ sB0p = (const u64*)sB0;

    u64 acc[32];
#pragma unroll
    for (int j = 0; j < 32; j++) acc[j] = sB0p[j];

#pragma unroll 4
    for (int c = 0; c < 128; c++) {
        const float xc = __ldg(xp + (size_t)c * HWLO);
        const u64 xx = pack2(xc, xc);
#pragma unroll
        for (int j = 0; j < 32; j++) acc[j] = fma2(sW0p[c * 32 + j], xx, acc[j]);
    }

    float a1[64];
#pragma unroll
    for (int j = 0; j < 32; j++) {
        float lo, hi; unpack2(acc[j], lo, hi);
        a1[2 * j] = eluf(lo); a1[2 * j + 1] = eluf(hi);
    }

    float a2[32]; dense2<64, 16, true >(sW1, sB1, a1, a2);
    float a3[16]; dense2<32, 8,  true >(sW2, sB2, a2, a3);
    float a4[8];  dense2<16, 4,  true >(sW3, sB3, a3, a4);
    float a5[4];  dense2<8,  2,  false>(sW4, sB4, a4, a5);  // no activation

    // final 4 -> 3, scalar
    float y[3];
#pragma unroll
    for (int o = 0; o < 3; o++) {
        float s = sBc[o];
#pragma unroll
        for (int c = 0; c < 4; c++) s += sWc[c * 3 + o] * a5[c];
        y[o] = s;
    }

    // ---- plane parameters -----------------------------------------------------
    const float theta = sigmoidf_fast(y[0]) * (PI_F / 6.0f);
    const float phi   = sigmoidf_fast(y[1]) * (PI_F * 2.0f);
    const float dist  = sigmoidf_fast(y[2]) * MAX_DEPTH;

    const float st = __sinf(theta), ct = __cosf(theta);
    const float sp = __sinf(phi),   cp = __cosf(phi);
    float nx = st * cp, ny = st * sp, nz = ct;
    const float inv = rsqrtf(nx * nx + ny * ny + nz * nz);
    nx *= inv; ny *= inv; nz *= inv;

    // ---- 8x8 upsampled depth block ---------------------------------------------
    const int h = hw / W8;
    const int w = hw - h * W8;
    float* __restrict__ op = out + ((size_t)b * HOUT + (size_t)h * 8) * WOUT + (size_t)w * 8;

#pragma unroll
    for (int i = 0; i < 8; i++) {
        const float vterm = ny * ((float)i - 3.5f) * 0.125f + nz;
        float row[8];
#pragma unroll
        for (int j = 0; j < 8; j++) {
            const float u = ((float)j - 3.5f) * 0.125f;
            row[j] = __fdividef(dist, nx * u + vterm);
        }
        float4* o4 = (float4*)(op + (size_t)i * WOUT);
        o4[0] = make_float4(row[0], row[1], row[2], row[3]);
        o4[1] = make_float4(row[4], row[5], row[6], row[7]);
    }
}

extern "C" void kernel_launch(void* const* d_in, const int* in_sizes, int n_in,
                              void* d_out, int out_size) {
    const float* x  = (const float*)d_in[0];
    const float* w0 = (const float*)d_in[1];
    const float* b0 = (const float*)d_in[2];
    const float* w1 = (const float*)d_in[3];
    const float* b1 = (const float*)d_in[4];
    const float* w2 = (const float*)d_in[5];
    const float* b2 = (const float*)d_in[6];
    const float* w3 = (const float*)d_in[7];
    const float* b3 = (const float*)d_in[8];
    const float* w4 = (const float*)d_in[9];
    const float* b4 = (const float*)d_in[10];
    const float* wc = (const float*)d_in[11];
    const float* bc = (const float*)d_in[12];
    float* out = (float*)d_out;

    lpg_fused_kernel<<<NPIX / 256, 256>>>(x, w0, b0, w1, b1, w2, b2, w3, b3,
                                          w4, b4, wc, bc, out);
}

// round 3
// speedup vs baseline: 1.6883x; 1.0058x over previous
#include <cuda_runtime.h>
#include <math.h>

#define NB   16
#define C0   128
#define H8   44
#define W8   144
#define HWLO (H8 * W8)          // 6336
#define NPIX (NB * HWLO)        // 101376 = 396 * 256
#define HOUT (H8 * 8)           // 352
#define WOUT (W8 * 8)           // 1152
#define PI_F 3.1415926535f
#define MAX_DEPTH 81.0f

typedef unsigned long long u64;

// ---------------- packed f32x2 helpers (sm_103a) -------------------------------
__device__ __forceinline__ u64 pack2(float lo, float hi) {
    u64 r; asm("mov.b64 %0, {%1, %2};" : "=l"(r) : "f"(lo), "f"(hi)); return r;
}
__device__ __forceinline__ void unpack2(u64 v, float& lo, float& hi) {
    asm("mov.b64 {%0, %1}, %2;" : "=f"(lo), "=f"(hi) : "l"(v));
}
__device__ __forceinline__ u64 fma2(u64 a, u64 b, u64 c) {
    u64 d; asm("fma.rn.f32x2 %0, %1, %2, %3;" : "=l"(d) : "l"(a), "l"(b), "l"(c));
    return d;
}

// ---------------- shared-weight loaders (transpose [O,C] -> [C,O]) -------------
template<int CIN, int COUT>
__device__ __forceinline__ void load_wT(const float* __restrict__ g, float* s, int t, int nt) {
    for (int i = t; i < CIN * COUT; i += nt) {
        int c = i / COUT, o = i % COUT;
        s[i] = g[o * CIN + c];
    }
}
__device__ __forceinline__ void load_vec(const float* __restrict__ g, float* s, int n, int t, int nt) {
    for (int i = t; i < n; i += nt) s[i] = g[i];
}

__device__ __forceinline__ float eluf(float v) {
    return (v > 0.0f) ? v : (__expf(v) - 1.0f);
}
__device__ __forceinline__ float sigmoidf_fast(float v) {
    return __fdividef(1.0f, 1.0f + __expf(-v));
}

// ---- packed dense layer with LDS.128 weight loads -----------------------------
// sW laid out [CIN][COUT] floats = [CIN][COUTP] u64 pairs; COUTP even.
template<int CIN, int COUTP, bool DO_ELU>
__device__ __forceinline__ void dense2v(const float* __restrict__ sW,
                                        const float* __restrict__ sB,
                                        const float* __restrict__ in,
                                        float* __restrict__ outv) {
    const ulonglong2* __restrict__ w4 = (const ulonglong2*)sW;   // 2 pairs / load
    const u64* __restrict__ b2 = (const u64*)sB;
    u64 acc[COUTP];
#pragma unroll
    for (int j = 0; j < COUTP; j++) acc[j] = b2[j];
#pragma unroll 4
    for (int c = 0; c < CIN; c++) {
        const u64 xx = pack2(in[c], in[c]);
#pragma unroll
        for (int q = 0; q < COUTP / 2; q++) {
            const ulonglong2 w = w4[c * (COUTP / 2) + q];
            acc[2 * q]     = fma2(w.x, xx, acc[2 * q]);
            acc[2 * q + 1] = fma2(w.y, xx, acc[2 * q + 1]);
        }
    }
#pragma unroll
    for (int j = 0; j < COUTP; j++) {
        float lo, hi; unpack2(acc[j], lo, hi);
        if (DO_ELU) { lo = eluf(lo); hi = eluf(hi); }
        outv[2 * j] = lo; outv[2 * j + 1] = hi;
    }
}

// ---------------------------------- kernel ------------------------------------
__global__ __launch_bounds__(256, 2) void lpg_fused_kernel(
    const float* __restrict__ x,
    const float* __restrict__ w0, const float* __restrict__ b0,
    const float* __restrict__ w1, const float* __restrict__ b1,
    const float* __restrict__ w2, const float* __restrict__ b2,
    const float* __restrict__ w3, const float* __restrict__ b3,
    const float* __restrict__ w4, const float* __restrict__ b4,
    const float* __restrict__ wc, const float* __restrict__ bc,
    float* __restrict__ out)
{
    __shared__ __align__(16) float sW0[128 * 64];
    __shared__ __align__(16) float sW1[64 * 32];
    __shared__ __align__(16) float sW2[32 * 16];
    __shared__ __align__(16) float sW3[16 * 8];
    __shared__ __align__(16) float sW4[8 * 4];
    __shared__ __align__(16) float sWc[4 * 3];
    __shared__ __align__(16) float sB0[64];
    __shared__ __align__(16) float sB1[32];
    __shared__ __align__(16) float sB2[16];
    __shared__ __align__(16) float sB3[8];
    __shared__ __align__(16) float sB4[4];
    __shared__ float sBc[3];

    const int t = threadIdx.x;
    load_wT<128, 64>(w0, sW0, t, 256);
    load_wT<64, 32>(w1, sW1, t, 256);
    load_wT<32, 16>(w2, sW2, t, 256);
    load_wT<16, 8>(w3, sW3, t, 256);
    load_wT<8, 4>(w4, sW4, t, 256);
    load_wT<4, 3>(wc, sWc, t, 256);
    load_vec(b0, sB0, 64, t, 256);
    load_vec(b1, sB1, 32, t, 256);
    load_vec(b2, sB2, 16, t, 256);
    load_vec(b3, sB3, 8, t, 256);
    load_vec(b4, sB4, 4, t, 256);
    load_vec(bc, sBc, 3, t, 256);
    __syncthreads();

    const int p  = blockIdx.x * 256 + t;     // grid is exact: NPIX/256 blocks
    const int b  = p / HWLO;
    const int hw = p - b * HWLO;

    // ---- layer 1: 128 -> 64 packed pairs, weights via LDS.128 -----------------
    const float* __restrict__ xp = x + (size_t)b * C0 * HWLO + hw;
    const ulonglong2* __restrict__ sW0v = (const ulonglong2*)sW0;  // [128][16]
    const u64* __restrict__ sB0p = (const u64*)sB0;

    u64 acc[32];
#pragma unroll
    for (int j = 0; j < 32; j++) acc[j] = sB0p[j];

#pragma unroll 4
    for (int c = 0; c < 128; c++) {
        const float xc = __ldg(xp + (size_t)c * HWLO);
        const u64 xx = pack2(xc, xc);
#pragma unroll
        for (int q = 0; q < 16; q++) {
            const ulonglong2 w = sW0v[c * 16 + q];
            acc[2 * q]     = fma2(w.x, xx, acc[2 * q]);
            acc[2 * q + 1] = fma2(w.y, xx, acc[2 * q + 1]);
        }
    }

    float a1[64];
#pragma unroll
    for (int j = 0; j < 32; j++) {
        float lo, hi; unpack2(acc[j], lo, hi);
        a1[2 * j] = eluf(lo); a1[2 * j + 1] = eluf(hi);
    }

    float a2[32]; dense2v<64, 16, true >(sW1, sB1, a1, a2);
    float a3[16]; dense2v<32, 8,  true >(sW2, sB2, a2, a3);
    float a4[8];  dense2v<16, 4,  true >(sW3, sB3, a3, a4);
    float a5[4];  dense2v<8,  2,  false>(sW4, sB4, a4, a5);  // no activation

    // final 4 -> 3, scalar
    float y[3];
#pragma unroll
    for (int o = 0; o < 3; o++) {
        float s = sBc[o];
#pragma unroll
        for (int c = 0; c < 4; c++) s += sWc[c * 3 + o] * a5[c];
        y[o] = s;
    }

    // ---- plane parameters ------------------------------------------------------
    const float theta = sigmoidf_fast(y[0]) * (PI_F / 6.0f);
    const float phi   = sigmoidf_fast(y[1]) * (PI_F * 2.0f);
    const float dist  = sigmoidf_fast(y[2]) * MAX_DEPTH;

    const float st = __sinf(theta), ct = __cosf(theta);
    const float sp = __sinf(phi),   cp = __cosf(phi);
    float nx = st * cp, ny = st * sp, nz = ct;
    const float inv = rsqrtf(nx * nx + ny * ny + nz * nz);
    nx *= inv; ny *= inv; nz *= inv;

    // ---- 8x8 upsampled depth block ----------------------------------------------
    const int h = hw / W8;
    const int w = hw - h * W8;
    float* __restrict__ op = out + ((size_t)b * HOUT + (size_t)h * 8) * WOUT + (size_t)w * 8;

#pragma unroll
    for (int i = 0; i < 8; i++) {
        const float vterm = ny * ((float)i - 3.5f) * 0.125f + nz;
        float row[8];
#pragma unroll
        for (int j = 0; j < 8; j++) {
            const float u = ((float)j - 3.5f) * 0.125f;
            row[j] = __fdividef(dist, nx * u + vterm);
        }
        float4* o4 = (float4*)(op + (size_t)i * WOUT);
        o4[0] = make_float4(row[0], row[1], row[2], row[3]);
        o4[1] = make_float4(row[4], row[5], row[6], row[7]);
    }
}

extern "C" void kernel_launch(void* const* d_in, const int* in_sizes, int n_in,
                              void* d_out, int out_size) {
    const float* x  = (const float*)d_in[0];
    const float* w0 = (const float*)d_in[1];
    const float* b0 = (const float*)d_in[2];
    const float* w1 = (const float*)d_in[3];
    const float* b1 = (const float*)d_in[4];
    const float* w2 = (const float*)d_in[5];
    const float* b2 = (const float*)d_in[6];
    const float* w3 = (const float*)d_in[7];
    const float* b3 = (const float*)d_in[8];
    const float* w4 = (const float*)d_in[9];
    const float* b4 = (const float*)d_in[10];
    const float* wc = (const float*)d_in[11];
    const float* bc = (const float*)d_in[12];
    float* out = (float*)d_out;

    lpg_fused_kernel<<<NPIX / 256, 256>>>(x, w0, b0, w1, b1, w2, b2, w3, b3,
                                          w4, b4, wc, bc, out);
}

// round 4
// speedup vs baseline: 1.8203x; 1.0782x over previous
#include <cuda_runtime.h>
#include <math.h>

#define NB    16
#define H8    44
#define W8    144
#define HWLO  (H8 * W8)        // 6336
#define HOUT  (H8 * 8)         // 352
#define WOUT  (W8 * 8)         // 1152
#define P     96               // pixels per CTA (66 tiles per image, exact)
#define NTILE (HWLO / P)       // 66
#define NTHR  192
#define PI_F  3.1415926535f
#define MAX_DEPTH 81.0f

typedef unsigned long long u64;

// ---- dynamic smem layout (float offsets) ----
#define OFF_XS   0              // x tile [128][96]            (12288 f)
#define OFF_A1S  0              // a1 [64][96]  (aliases dead xs)
#define OFF_A2S  6144           // a2 [32][96]  (aliases dead xs)
#define OFF_WT0  12288          // [128][68] padded transpose  (8704 f)
#define OFF_WT1  20992          // [64][36]  padded transpose  (2304 f)
#define OFF_WT2  23296          // [32][16]                    (512 f)
#define OFF_WT3  23808          // [16][8]                     (128 f)
#define OFF_WT4  23936          // [8][4]                      (32 f)
#define OFF_WC   23968          // [4][3] (+pad)               (16 f)
#define OFF_B0   23984          // 64
#define OFF_B1   24048          // 32
#define OFF_B2   24080          // 16
#define OFF_B3   24096          // 8
#define OFF_B4   24104          // 4
#define OFF_BC   24108          // 3 (+pad)
#define SMEM_FLOATS 24112
#define SMEM_BYTES  (SMEM_FLOATS * 4)

// ---------------- packed f32x2 helpers (sm_103a) -------------------------------
__device__ __forceinline__ u64 pack2(float lo, float hi) {
    u64 r; asm("mov.b64 %0, {%1, %2};" : "=l"(r) : "f"(lo), "f"(hi)); return r;
}
__device__ __forceinline__ void unpack2(u64 v, float& lo, float& hi) {
    asm("mov.b64 {%0, %1}, %2;" : "=f"(lo), "=f"(hi) : "l"(v));
}
__device__ __forceinline__ u64 fma2(u64 a, u64 b, u64 c) {
    u64 d; asm("fma.rn.f32x2 %0, %1, %2, %3;" : "=l"(d) : "l"(a), "l"(b), "l"(c));
    return d;
}

__device__ __forceinline__ float eluf(float v) {
    return (v > 0.0f) ? v : (__expf(v) - 1.0f);
}
__device__ __forceinline__ float sigmoidf_fast(float v) {
    return __fdividef(1.0f, 1.0f + __expf(-v));
}

// ---- per-pixel packed dense layer (tail), weights [CIN][COUT] in smem ---------
template<int CIN, int COUTP, bool DO_ELU>
__device__ __forceinline__ void dense2v(const float* __restrict__ sW,
                                        const float* __restrict__ sB,
                                        const float* __restrict__ in,
                                        float* __restrict__ outv) {
    const ulonglong2* __restrict__ w4 = (const ulonglong2*)sW;
    const u64* __restrict__ b2 = (const u64*)sB;
    u64 acc[COUTP];
#pragma unroll
    for (int j = 0; j < COUTP; j++) acc[j] = b2[j];
#pragma unroll 4
    for (int c = 0; c < CIN; c++) {
        const u64 xx = pack2(in[c], in[c]);
#pragma unroll
        for (int q = 0; q < COUTP / 2; q++) {
            const ulonglong2 w = w4[c * (COUTP / 2) + q];
            acc[2 * q]     = fma2(w.x, xx, acc[2 * q]);
            acc[2 * q + 1] = fma2(w.y, xx, acc[2 * q + 1]);
        }
    }
#pragma unroll
    for (int j = 0; j < COUTP; j++) {
        float lo, hi; unpack2(acc[j], lo, hi);
        if (DO_ELU) { lo = eluf(lo); hi = eluf(hi); }
        outv[2 * j] = lo; outv[2 * j + 1] = hi;
    }
}

// ---------------------------------- kernel ------------------------------------
__global__ __launch_bounds__(NTHR, 2) void lpg_fused_kernel(
    const float* __restrict__ x,
    const float* __restrict__ w0, const float* __restrict__ b0,
    const float* __restrict__ w1, const float* __restrict__ b1,
    const float* __restrict__ w2, const float* __restrict__ b2,
    const float* __restrict__ w3, const float* __restrict__ b3,
    const float* __restrict__ w4, const float* __restrict__ b4,
    const float* __restrict__ wc, const float* __restrict__ bc,
    float* __restrict__ out)
{
    extern __shared__ float sm[];
    float* xs   = sm + OFF_XS;
    float* a1s  = sm + OFF_A1S;
    float* a2s  = sm + OFF_A2S;
    float* wT0  = sm + OFF_WT0;
    float* wT1  = sm + OFF_WT1;
    float* wT2  = sm + OFF_WT2;
    float* wT3  = sm + OFF_WT3;
    float* wT4  = sm + OFF_WT4;
    float* sWc  = sm + OFF_WC;
    float* sB0  = sm + OFF_B0;
    float* sB1  = sm + OFF_B1;
    float* sB2  = sm + OFF_B2;
    float* sB3  = sm + OFF_B3;
    float* sB4  = sm + OFF_B4;
    float* sBc  = sm + OFF_BC;

    const int t    = threadIdx.x;
    const int tile = blockIdx.x;     // 0..65
    const int b    = blockIdx.y;     // 0..15
    const int hw0  = tile * P;

    // ---- stage weights (padded transposes) and x tile --------------------------
    for (int j = t; j < 128 * 64; j += NTHR) {       // w0 [64][128] -> wT0 [c][68]
        int o = j >> 7, c = j & 127;
        wT0[c * 68 + o] = w0[j];
    }
    for (int j = t; j < 64 * 32; j += NTHR) {        // w1 -> wT1 [c][36]
        int o = j >> 6, c = j & 63;
        wT1[c * 36 + o] = w1[j];
    }
    for (int j = t; j < 32 * 16; j += NTHR) { int o = j >> 5, c = j & 31; wT2[c * 16 + o] = w2[j]; }
    for (int j = t; j < 16 * 8;  j += NTHR) { int o = j >> 4, c = j & 15; wT3[c * 8  + o] = w3[j]; }
    if (t < 32) { int o = t >> 3, c = t & 7;  wT4[c * 4 + o] = w4[t]; }
    if (t < 12) { int o = t >> 2, c = t & 3;  sWc[c * 3 + o] = wc[t]; }
    if (t < 64) sB0[t] = b0[t];
    if (t < 32) sB1[t] = b1[t];
    if (t < 16) sB2[t] = b2[t];
    if (t < 8)  sB3[t] = b3[t];
    if (t < 4)  sB4[t] = b4[t];
    if (t < 3)  sBc[t] = bc[t];

    const float* __restrict__ xb = x + (size_t)b * 128 * HWLO + hw0;
    for (int j = t; j < 128 * 24; j += NTHR) {       // 24 float4 per channel row
        int c = j / 24, col = j % 24;
        *(float4*)(xs + c * 96 + col * 4) = __ldg((const float4*)(xb + (size_t)c * HWLO + col * 4));
    }
    __syncthreads();

    const int pg = t % 24;   // pixel group: pixels pg*4 .. pg*4+3
    const int og = t / 24;   // out group (0..7)

    // ---- layer 1 blocked: 4 pix x 8 out per thread ------------------------------
    u64 acc[4][4];           // [pixel][out-pair]
    {
        const u64* b0p = (const u64*)sB0;
#pragma unroll
        for (int i = 0; i < 4; i++)
#pragma unroll
            for (int j = 0; j < 4; j++) acc[i][j] = b0p[og * 4 + j];

#pragma unroll 4
        for (int c = 0; c < 128; c++) {
            const float4 xv = *(const float4*)(xs + c * 96 + pg * 4);
            const float* wr = wT0 + c * 68 + og * 8;
            const ulonglong2 wa = *(const ulonglong2*)wr;
            const ulonglong2 wb = *(const ulonglong2*)(wr + 4);
            const u64 xx0 = pack2(xv.x, xv.x), xx1 = pack2(xv.y, xv.y);
            const u64 xx2 = pack2(xv.z, xv.z), xx3 = pack2(xv.w, xv.w);
            acc[0][0] = fma2(wa.x, xx0, acc[0][0]); acc[0][1] = fma2(wa.y, xx0, acc[0][1]);
            acc[0][2] = fma2(wb.x, xx0, acc[0][2]); acc[0][3] = fma2(wb.y, xx0, acc[0][3]);
            acc[1][0] = fma2(wa.x, xx1, acc[1][0]); acc[1][1] = fma2(wa.y, xx1, acc[1][1]);
            acc[1][2] = fma2(wb.x, xx1, acc[1][2]); acc[1][3] = fma2(wb.y, xx1, acc[1][3]);
            acc[2][0] = fma2(wa.x, xx2, acc[2][0]); acc[2][1] = fma2(wa.y, xx2, acc[2][1]);
            acc[2][2] = fma2(wb.x, xx2, acc[2][2]); acc[2][3] = fma2(wb.y, xx2, acc[2][3]);
            acc[3][0] = fma2(wa.x, xx3, acc[3][0]); acc[3][1] = fma2(wa.y, xx3, acc[3][1]);
            acc[3][2] = fma2(wb.x, xx3, acc[3][2]); acc[3][3] = fma2(wb.y, xx3, acc[3][3]);
        }
    }
    __syncthreads();         // all xs reads done before a1s overwrite

    // ELU + scatter a1 fragment to smem [64][96]
#pragma unroll
    for (int j = 0; j < 4; j++) {
        const int o0 = og * 8 + 2 * j;
#pragma unroll
        for (int i = 0; i < 4; i++) {
            float lo, hi; unpack2(acc[i][j], lo, hi);
            const int px = pg * 4 + i;
            a1s[o0 * 96 + px]       = eluf(lo);
            a1s[(o0 + 1) * 96 + px] = eluf(hi);
        }
    }
    __syncthreads();

    // ---- layer 2 blocked: 4 pix x 4 out per thread ------------------------------
    u64 acc2[4][2];
    {
        const u64* b1p = (const u64*)sB1;
#pragma unroll
        for (int i = 0; i < 4; i++)
#pragma unroll
            for (int j = 0; j < 2; j++) acc2[i][j] = b1p[og * 2 + j];

#pragma unroll 4
        for (int c = 0; c < 64; c++) {
            const float4 av = *(const float4*)(a1s + c * 96 + pg * 4);
            const ulonglong2 w = *(const ulonglong2*)(wT1 + c * 36 + og * 4);
            const u64 xx0 = pack2(av.x, av.x), xx1 = pack2(av.y, av.y);
            const u64 xx2 = pack2(av.z, av.z), xx3 = pack2(av.w, av.w);
            acc2[0][0] = fma2(w.x, xx0, acc2[0][0]); acc2[0][1] = fma2(w.y, xx0, acc2[0][1]);
            acc2[1][0] = fma2(w.x, xx1, acc2[1][0]); acc2[1][1] = fma2(w.y, xx1, acc2[1][1]);
            acc2[2][0] = fma2(w.x, xx2, acc2[2][0]); acc2[2][1] = fma2(w.y, xx2, acc2[2][1]);
            acc2[3][0] = fma2(w.x, xx3, acc2[3][0]); acc2[3][1] = fma2(w.y, xx3, acc2[3][1]);
        }
    }
    // a2s region is disjoint from a1s; other threads may still read a1s — safe
#pragma unroll
    for (int j = 0; j < 2; j++) {
        const int o0 = og * 4 + 2 * j;
#pragma unroll
        for (int i = 0; i < 4; i++) {
            float lo, hi; unpack2(acc2[i][j], lo, hi);
            const int px = pg * 4 + i;
            a2s[o0 * 96 + px]       = eluf(lo);
            a2s[(o0 + 1) * 96 + px] = eluf(hi);
        }
    }
    __syncthreads();

    // ---- tail per pixel (threads 0..95) -----------------------------------------
    if (t < P) {
        float a2v[32];
#pragma unroll
        for (int c = 0; c < 32; c++) a2v[c] = a2s[c * 96 + t];

        float a3[16]; dense2v<32, 8, true >(wT2, sB2, a2v, a3);
        float a4[8];  dense2v<16, 4, true >(wT3, sB3, a3, a4);
        float a5[4];  dense2v<8,  2, false>(wT4, sB4, a4, a5);

        float y[3];
#pragma unroll
        for (int o = 0; o < 3; o++) {
            float s = sBc[o];
#pragma unroll
            for (int c = 0; c < 4; c++) s += sWc[c * 3 + o] * a5[c];
            y[o] = s;
        }

        const float theta = sigmoidf_fast(y[0]) * (PI_F / 6.0f);
        const float phi   = sigmoidf_fast(y[1]) * (PI_F * 2.0f);
        const float dist  = sigmoidf_fast(y[2]) * MAX_DEPTH;

        const float st = __sinf(theta), ct = __cosf(theta);
        const float sp = __sinf(phi),   cp = __cosf(phi);
        float nx = st * cp, ny = st * sp, nz = ct;
        const float inv = rsqrtf(nx * nx + ny * ny + nz * nz);
        nx *= inv; ny *= inv; nz *= inv;

        const int hw = hw0 + t;
        const int h  = hw / W8;
        const int w  = hw - h * W8;
        float* __restrict__ op = out + ((size_t)b * HOUT + (size_t)h * 8) * WOUT + (size_t)w * 8;

#pragma unroll
        for (int i = 0; i < 8; i++) {
            const float vterm = ny * ((float)i - 3.5f) * 0.125f + nz;
            float row[8];
#pragma unroll
            for (int j = 0; j < 8; j++) {
                const float u = ((float)j - 3.5f) * 0.125f;
                row[j] = __fdividef(dist, nx * u + vterm);
            }
            float4* o4 = (float4*)(op + (size_t)i * WOUT);
            o4[0] = make_float4(row[0], row[1], row[2], row[3]);
            o4[1] = make_float4(row[4], row[5], row[6], row[7]);
        }
    }
}

extern "C" void kernel_launch(void* const* d_in, const int* in_sizes, int n_in,
                              void* d_out, int out_size) {
    const float* x  = (const float*)d_in[0];
    const float* w0 = (const float*)d_in[1];
    const float* b0 = (const float*)d_in[2];
    const float* w1 = (const float*)d_in[3];
    const float* b1 = (const float*)d_in[4];
    const float* w2 = (const float*)d_in[5];
    const float* b2 = (const float*)d_in[6];
    const float* w3 = (const float*)d_in[7];
    const float* b3 = (const float*)d_in[8];
    const float* w4 = (const float*)d_in[9];
    const float* b4 = (const float*)d_in[10];
    const float* wc = (const float*)d_in[11];
    const float* bc = (const float*)d_in[12];
    float* out = (float*)d_out;

    cudaFuncSetAttribute(lpg_fused_kernel,
                         cudaFuncAttributeMaxDynamicSharedMemorySize, SMEM_BYTES);

    dim3 grid(NTILE, NB);
    lpg_fused_kernel<<<grid, NTHR, SMEM_BYTES>>>(x, w0, b0, w1, b1, w2, b2,
                                                 w3, b3, w4, b4, wc, bc, out);
}

// round 5
// speedup vs baseline: 1.8251x; 1.0026x over previous
#include <cuda_runtime.h>
#include <math.h>

#define NB    16
#define H8    44
#define W8    144
#define HWLO  (H8 * W8)        // 6336
#define HOUT  (H8 * 8)         // 352
#define WOUT  (W8 * 8)         // 1152
#define P     64               // pixels per CTA; 6336/64 = 99 tiles per image
#define NTILE (HWLO / P)       // 99
#define NTHR  256
#define PI_F  3.1415926535f
#define MAX_DEPTH 81.0f

typedef unsigned long long u64;

// ---- dynamic smem layout (float offsets) ----
#define OFF_WT0  0              // [128][68]  (8704 f)  layer-1 weights, transposed+padded
#define OFF_WT1  8704           // [64][36]   (2304 f)
#define OFF_WT2  11008          // [32][16]   (512 f)
#define OFF_WT3  11520          // [16][8]    (128 f)
#define OFF_WT4  11648          // [8][4]     (32 f)
#define OFF_WC   11680          // [4][3]+pad (16 f)
#define OFF_B0   11696          // 64
#define OFF_B1   11760          // 32
#define OFF_B2   11792          // 16
#define OFF_B3   11808          // 8
#define OFF_B4   11816          // 4
#define OFF_BC   11820          // 4
#define OFF_A1S  11824          // [64][64]   (4096 f)
#define OFF_A2S  15920          // [32][64]   (2048 f)
#define SMEM_FLOATS 17968
#define SMEM_BYTES  (SMEM_FLOATS * 4)   // 71872 B -> 3 CTAs/SM

// ---------------- packed f32x2 helpers (sm_103a) -------------------------------
__device__ __forceinline__ u64 pack2(float lo, float hi) {
    u64 r; asm("mov.b64 %0, {%1, %2};" : "=l"(r) : "f"(lo), "f"(hi)); return r;
}
__device__ __forceinline__ void unpack2(u64 v, float& lo, float& hi) {
    asm("mov.b64 {%0, %1}, %2;" : "=f"(lo), "=f"(hi) : "l"(v));
}
__device__ __forceinline__ u64 fma2(u64 a, u64 b, u64 c) {
    u64 d; asm("fma.rn.f32x2 %0, %1, %2, %3;" : "=l"(d) : "l"(a), "l"(b), "l"(c));
    return d;
}

__device__ __forceinline__ float eluf(float v) {
    return (v > 0.0f) ? v : (__expf(v) - 1.0f);
}
__device__ __forceinline__ float sigmoidf_fast(float v) {
    return __fdividef(1.0f, 1.0f + __expf(-v));
}

// ---------------------------------- kernel ------------------------------------
__global__ __launch_bounds__(NTHR, 3) void lpg_fused_kernel(
    const float* __restrict__ x,
    const float* __restrict__ w0, const float* __restrict__ b0,
    const float* __restrict__ w1, const float* __restrict__ b1,
    const float* __restrict__ w2, const float* __restrict__ b2,
    const float* __restrict__ w3, const float* __restrict__ b3,
    const float* __restrict__ w4, const float* __restrict__ b4,
    const float* __restrict__ wc, const float* __restrict__ bc,
    float* __restrict__ out)
{
    extern __shared__ float sm[];
    float* wT0 = sm + OFF_WT0;
    float* wT1 = sm + OFF_WT1;
    float* wT2 = sm + OFF_WT2;
    float* wT3 = sm + OFF_WT3;
    float* wT4 = sm + OFF_WT4;
    float* sWc = sm + OFF_WC;
    float* sB0 = sm + OFF_B0;
    float* sB1 = sm + OFF_B1;
    float* sB2 = sm + OFF_B2;
    float* sB3 = sm + OFF_B3;
    float* sB4 = sm + OFF_B4;
    float* sBc = sm + OFF_BC;
    float* a1s = sm + OFF_A1S;   // [64][64]
    float* a2s = sm + OFF_A2S;   // [32][64]

    const int t    = threadIdx.x;
    const int tile = blockIdx.x;     // 0..98
    const int b    = blockIdx.y;     // 0..15
    const int hw0  = tile * P;

    // ---- stage weights (transposed, wT0/wT1 row-padded for STS banks) ----------
    for (int j = t; j < 128 * 64; j += NTHR) {  // w0 [64][128] -> wT0 [c][68]
        int o = j >> 7, c = j & 127;
        wT0[c * 68 + o] = w0[j];
    }
    for (int j = t; j < 64 * 32; j += NTHR) {   // w1 [32][64] -> wT1 [c][36]
        int o = j >> 6, c = j & 63;
        wT1[c * 36 + o] = w1[j];
    }
    for (int j = t; j < 32 * 16; j += NTHR) { int o = j >> 5, c = j & 31; wT2[c * 16 + o] = w2[j]; }
    if (t < 128) { int o = t >> 4, c = t & 15; wT3[c * 8 + o] = w3[t]; }
    if (t < 32)  { int o = t >> 3, c = t & 7;  wT4[c * 4 + o] = w4[t]; }
    if (t < 12)  { int o = t >> 2, c = t & 3;  sWc[c * 3 + o] = wc[t]; }
    if (t < 64) sB0[t] = b0[t];
    if (t < 32) sB1[t] = b1[t];
    if (t < 16) sB2[t] = b2[t];
    if (t < 8)  sB3[t] = b3[t];
    if (t < 4)  sB4[t] = b4[t];
    if (t < 3)  sBc[t] = bc[t];
    __syncthreads();

    const int pg = t & 31;    // pixel pair: pixels 2pg, 2pg+1
    const int og = t >> 5;    // out group 0..7 — constant within a warp

    // ---- layer 1: 128 -> 64, 2 pix x 8 outs per thread, x from global ----------
    const float* __restrict__ xp = x + (size_t)b * 128 * HWLO + hw0 + 2 * pg;
    const float* __restrict__ wrow0 = wT0 + og * 8;
    {
        const u64* b0p = (const u64*)sB0;
        u64 acc0[4], acc1[4];                  // [out-pair] for pixel 0 / pixel 1
#pragma unroll
        for (int j = 0; j < 4; j++) { acc0[j] = b0p[og * 4 + j]; acc1[j] = acc0[j]; }

#pragma unroll 4
        for (int c = 0; c < 128; c++) {
            const float2 xv = __ldg((const float2*)(xp + (size_t)c * HWLO));
            const ulonglong2 wa = *(const ulonglong2*)(wrow0 + c * 68);
            const ulonglong2 wb = *(const ulonglong2*)(wrow0 + c * 68 + 4);
            const u64 xx0 = pack2(xv.x, xv.x);
            const u64 xx1 = pack2(xv.y, xv.y);
            acc0[0] = fma2(wa.x, xx0, acc0[0]); acc0[1] = fma2(wa.y, xx0, acc0[1]);
            acc0[2] = fma2(wb.x, xx0, acc0[2]); acc0[3] = fma2(wb.y, xx0, acc0[3]);
            acc1[0] = fma2(wa.x, xx1, acc1[0]); acc1[1] = fma2(wa.y, xx1, acc1[1]);
            acc1[2] = fma2(wb.x, xx1, acc1[2]); acc1[3] = fma2(wb.y, xx1, acc1[3]);
        }
        // ELU + scatter: for each of 8 outs write float2 {pix0, pix1}
#pragma unroll
        for (int j = 0; j < 4; j++) {
            float l0, h0, l1, h1;
            unpack2(acc0[j], l0, h0); unpack2(acc1[j], l1, h1);
            const int o0 = og * 8 + 2 * j;
            *(float2*)(a1s + o0 * 64 + 2 * pg)       = make_float2(eluf(l0), eluf(l1));
            *(float2*)(a1s + (o0 + 1) * 64 + 2 * pg) = make_float2(eluf(h0), eluf(h1));
        }
    }
    __syncthreads();

    // ---- layer 2: 64 -> 32, 2 pix x 4 outs per thread --------------------------
    {
        const u64* b1p = (const u64*)sB1;
        const float* __restrict__ wrow1 = wT1 + og * 4;
        u64 acc0[2], acc1[2];
#pragma unroll
        for (int j = 0; j < 2; j++) { acc0[j] = b1p[og * 2 + j]; acc1[j] = acc0[j]; }

#pragma unroll 4
        for (int c = 0; c < 64; c++) {
            const float2 av = *(const float2*)(a1s + c * 64 + 2 * pg);
            const ulonglong2 w = *(const ulonglong2*)(wrow1 + c * 36);
            const u64 xx0 = pack2(av.x, av.x);
            const u64 xx1 = pack2(av.y, av.y);
            acc0[0] = fma2(w.x, xx0, acc0[0]); acc0[1] = fma2(w.y, xx0, acc0[1]);
            acc1[0] = fma2(w.x, xx1, acc1[0]); acc1[1] = fma2(w.y, xx1, acc1[1]);
        }
#pragma unroll
        for (int j = 0; j < 2; j++) {
            float l0, h0, l1, h1;
            unpack2(acc0[j], l0, h0); unpack2(acc1[j], l1, h1);
            const int o0 = og * 4 + 2 * j;
            *(float2*)(a2s + o0 * 64 + 2 * pg)       = make_float2(eluf(l0), eluf(l1));
            *(float2*)(a2s + (o0 + 1) * 64 + 2 * pg) = make_float2(eluf(h0), eluf(h1));
        }
    }
    __syncthreads();

    // ---- tail: 4 threads per pixel, redundant small-layer compute --------------
    const int px  = t >> 2;       // 0..63
    const int sub = t & 3;        // row-pair selector

    // layer 3: 32 -> 16 (a2 read strided from smem, value used once)
    float a3[16];
    {
        const u64* b2p = (const u64*)sB2;
        u64 acc[8];
#pragma unroll
        for (int j = 0; j < 8; j++) acc[j] = b2p[j];
#pragma unroll 4
        for (int c = 0; c < 32; c++) {
            const float v = a2s[c * 64 + px];
            const u64 xx = pack2(v, v);
            const ulonglong2 wa = *(const ulonglong2*)(wT2 + c * 16);
            const ulonglong2 wb = *(const ulonglong2*)(wT2 + c * 16 + 4);
            const ulonglong2 wc2 = *(const ulonglong2*)(wT2 + c * 16 + 8);
            const ulonglong2 wd = *(const ulonglong2*)(wT2 + c * 16 + 12);
            acc[0] = fma2(wa.x, xx, acc[0]); acc[1] = fma2(wa.y, xx, acc[1]);
            acc[2] = fma2(wb.x, xx, acc[2]); acc[3] = fma2(wb.y, xx, acc[3]);
            acc[4] = fma2(wc2.x, xx, acc[4]); acc[5] = fma2(wc2.y, xx, acc[5]);
            acc[6] = fma2(wd.x, xx, acc[6]); acc[7] = fma2(wd.y, xx, acc[7]);
        }
#pragma unroll
        for (int j = 0; j < 8; j++) {
            float lo, hi; unpack2(acc[j], lo, hi);
            a3[2 * j] = eluf(lo); a3[2 * j + 1] = eluf(hi);
        }
    }

    // layer 4: 16 -> 8
    float a4[8];
    {
        const u64* b3p = (const u64*)sB3;
        u64 acc[4];
#pragma unroll
        for (int j = 0; j < 4; j++) acc[j] = b3p[j];
#pragma unroll
        for (int c = 0; c < 16; c++) {
            const u64 xx = pack2(a3[c], a3[c]);
            const ulonglong2 wa = *(const ulonglong2*)(wT3 + c * 8);
            const ulonglong2 wb = *(const ulonglong2*)(wT3 + c * 8 + 4);
            acc[0] = fma2(wa.x, xx, acc[0]); acc[1] = fma2(wa.y, xx, acc[1]);
            acc[2] = fma2(wb.x, xx, acc[2]); acc[3] = fma2(wb.y, xx, acc[3]);
        }
#pragma unroll
        for (int j = 0; j < 4; j++) {
            float lo, hi; unpack2(acc[j], lo, hi);
            a4[2 * j] = eluf(lo); a4[2 * j + 1] = eluf(hi);
        }
    }

    // layer 5: 8 -> 4 (no activation)
    float a5[4];
    {
        const u64* b4p = (const u64*)sB4;
        u64 acc[2];
        acc[0] = b4p[0]; acc[1] = b4p[1];
#pragma unroll
        for (int c = 0; c < 8; c++) {
            const u64 xx = pack2(a4[c], a4[c]);
            const ulonglong2 w = *(const ulonglong2*)(wT4 + c * 4);
            acc[0] = fma2(w.x, xx, acc[0]); acc[1] = fma2(w.y, xx, acc[1]);
        }
        unpack2(acc[0], a5[0], a5[1]); unpack2(acc[1], a5[2], a5[3]);
    }

    // final 4 -> 3
    float y[3];
#pragma unroll
    for (int o = 0; o < 3; o++) {
        float s = sBc[o];
#pragma unroll
        for (int c = 0; c < 4; c++) s += sWc[c * 3 + o] * a5[c];
        y[o] = s;
    }

    // ---- plane parameters -------------------------------------------------------
    const float theta = sigmoidf_fast(y[0]) * (PI_F / 6.0f);
    const float phi   = sigmoidf_fast(y[1]) * (PI_F * 2.0f);
    const float dist  = sigmoidf_fast(y[2]) * MAX_DEPTH;

    const float st = __sinf(theta), ct = __cosf(theta);
    const float sp = __sinf(phi),   cp = __cosf(phi);
    float nx = st * cp, ny = st * sp, nz = ct;
    const float inv = rsqrtf(nx * nx + ny * ny + nz * nz);
    nx *= inv; ny *= inv; nz *= inv;

    // ---- this thread writes rows 2*sub and 2*sub+1 of the 8x8 block --------------
    const int hw = hw0 + px;
    const int h  = hw / W8;
    const int w  = hw - h * W8;
    float* __restrict__ op = out + ((size_t)b * HOUT + (size_t)h * 8) * WOUT + (size_t)w * 8;

#pragma unroll
    for (int r = 0; r < 2; r++) {
        const int i = sub * 2 + r;
        const float vterm = ny * ((float)i - 3.5f) * 0.125f + nz;
        float row[8];
#pragma unroll
        for (int j = 0; j < 8; j++) {
            const float u = ((float)j - 3.5f) * 0.125f;
            row[j] = __fdividef(dist, nx * u + vterm);
        }
        float4* o4 = (float4*)(op + (size_t)i * WOUT);
        o4[0] = make_float4(row[0], row[1], row[2], row[3]);
        o4[1] = make_float4(row[4], row[5], row[6], row[7]);
    }
}

extern "C" void kernel_launch(void* const* d_in, const int* in_sizes, int n_in,
                              void* d_out, int out_size) {
    const float* x  = (const float*)d_in[0];
    const float* w0 = (const float*)d_in[1];
    const float* b0 = (const float*)d_in[2];
    const float* w1 = (const float*)d_in[3];
    const float* b1 = (const float*)d_in[4];
    const float* w2 = (const float*)d_in[5];
    const float* b2 = (const float*)d_in[6];
    const float* w3 = (const float*)d_in[7];
    const float* b3 = (const float*)d_in[8];
    const float* w4 = (const float*)d_in[9];
    const float* b4 = (const float*)d_in[10];
    const float* wc = (const float*)d_in[11];
    const float* bc = (const float*)d_in[12];
    float* out = (float*)d_out;

    cudaFuncSetAttribute(lpg_fused_kernel,
                         cudaFuncAttributeMaxDynamicSharedMemorySize, SMEM_BYTES);

    dim3 grid(NTILE, NB);
    lpg_fused_kernel<<<grid, NTHR, SMEM_BYTES>>>(x, w0, b0, w1, b1, w2, b2,
                                                 w3, b3, w4, b4, wc, bc, out);
}